// round 1
// baseline (speedup 1.0000x reference)
#include <cuda_runtime.h>
#include <math.h>

#define NTOK 32768
#define INF  204
#define HD   128
#define NM   4
#define AD   14
#define KD   32
#define TT   64

// smem layout (floats)
#define XA_OFF 0          // [64][132]
#define HS_OFF 8448       // [64][132]
#define C_OFF  16896      // X [64][212] -> later inn [64][132] + hn [64][132]
#define HN_OFF (C_OFF + 8448)
#define RZ_OFF 33792      // [64][256]
#define E_OFF  50176      // weight staging, up to 16*256 floats
#define SMEM_FLOATS 54272
#define SMEM_BYTES (SMEM_FLOATS * 4)

__device__ int g_cnt[NM];
__device__ int g_list[NM * NTOK];

__global__ void reset_kernel() {
    if (threadIdx.x < NM) g_cnt[threadIdx.x] = 0;
}

// ---------------- router: compute argmax mechanism per token, bucket ----------------
__global__ void __launch_bounds__(128) router_kernel(
    const float* __restrict__ hidden,
    const float* __restrict__ w1, const float* __restrict__ b1,
    const float* __restrict__ w2, const float* __restrict__ b2,
    const float* __restrict__ w3, const float* __restrict__ b3,
    const float* __restrict__ wq, const float* __restrict__ bq,
    const float* __restrict__ wk, const float* __restrict__ bk,
    const float* __restrict__ mkeys,
    const float* __restrict__ unif)
{
    __shared__ float w1s[HD * KD];
    __shared__ float w2s[KD * KD];
    __shared__ float w3s[KD * KD];
    __shared__ float wqs[KD * KD];
    __shared__ float kps[NM * KD];
    const int tid = threadIdx.x;

    for (int i = tid; i < HD * KD; i += 128) w1s[i] = w1[i];
    for (int i = tid; i < KD * KD; i += 128) {
        w2s[i] = w2[i]; w3s[i] = w3[i]; wqs[i] = wq[i];
    }
    if (tid < NM * KD) {
        int m = tid / KD, j = tid % KD;
        float acc = bk[j];
        #pragma unroll
        for (int k = 0; k < KD; k++) acc = fmaf(mkeys[m * KD + k], wk[k * KD + j], acc);
        kps[tid] = acc;
    }
    __syncthreads();

    const int t = blockIdx.x * 128 + tid;
    const float* h = hidden + (size_t)t * HD;

    float q1[KD];
    #pragma unroll
    for (int j = 0; j < KD; j++) q1[j] = b1[j];
    for (int k = 0; k < HD; k++) {
        float hk = __ldg(h + k);
        #pragma unroll
        for (int j = 0; j < KD; j++) q1[j] = fmaf(hk, w1s[k * KD + j], q1[j]);
    }
    #pragma unroll
    for (int j = 0; j < KD; j++) q1[j] = fmaxf(q1[j], 0.f);

    float q2[KD];
    #pragma unroll
    for (int j = 0; j < KD; j++) {
        float acc = b2[j];
        #pragma unroll
        for (int k = 0; k < KD; k++) acc = fmaf(q1[k], w2s[k * KD + j], acc);
        q2[j] = fmaxf(acc, 0.f);
    }
    float q3[KD];
    #pragma unroll
    for (int j = 0; j < KD; j++) {
        float acc = b3[j];
        #pragma unroll
        for (int k = 0; k < KD; k++) acc = fmaf(q2[k], w3s[k * KD + j], acc);
        q3[j] = acc;
    }
    float qpv[KD];
    #pragma unroll
    for (int j = 0; j < KD; j++) {
        float acc = bq[j];
        #pragma unroll
        for (int k = 0; k < KD; k++) acc = fmaf(q3[k], wqs[k * KD + j], acc);
        qpv[j] = acc;
    }

    float l[NM];
    #pragma unroll
    for (int mm = 0; mm < NM; mm++) {
        float acc = 0.f;
        #pragma unroll
        for (int j = 0; j < KD; j++) acc = fmaf(qpv[j], kps[mm * KD + j], acc);
        l[mm] = acc * 0.17677669529663687f;  // 1/sqrt(32)
    }
    float mx = fmaxf(fmaxf(l[0], l[1]), fmaxf(l[2], l[3]));
    float s = 0.f;
    #pragma unroll
    for (int mm = 0; mm < NM; mm++) { l[mm] = expf(l[mm] - mx); s += l[mm]; }
    float inv = 1.f / s;

    float best = -1e30f; int sel = 0;
    #pragma unroll
    for (int mm = 0; mm < NM; mm++) {
        float u = unif[(size_t)t * NM + mm];
        float g = -logf(-logf(u + 1e-10f) + 1e-10f);
        float y = fmaf(l[mm], inv, g);
        if (y > best) { best = y; sel = mm; }   // first-max on ties, like jnp.argmax
    }
    int pos = atomicAdd(&g_cnt[sel], 1);
    g_list[sel * NTOK + pos] = t;
}

// ---------------- main: fused fc1 -> GRU -> fc2 per 64-token tile of one mech ----------------
__global__ void __launch_bounds__(256) main_kernel(
    const float* __restrict__ x_in, const float* __restrict__ hidden,
    const float* __restrict__ fc1w, const float* __restrict__ fc1b,
    const float* __restrict__ wih,  const float* __restrict__ whh,
    const float* __restrict__ bih,  const float* __restrict__ bhh,
    const float* __restrict__ fc2w, const float* __restrict__ fc2b,
    float* __restrict__ out_q, float* __restrict__ out_h)
{
    extern __shared__ float S[];
    __shared__ int sidx[TT];
    const int m = blockIdx.y;
    const int cnt = g_cnt[m];
    const int base = blockIdx.x * TT;
    if (base >= cnt) return;
    const int nvalid = min(TT, cnt - base);
    const int tid = threadIdx.x;

    if (tid < TT) {
        int p = base + tid;
        if (p > cnt - 1) p = cnt - 1;
        sidx[tid] = g_list[m * NTOK + p];
    }
    __syncthreads();

    // gather X [64][204] (stride 212) and H [64][128] (stride 132)
    for (int i = tid; i < TT * 51; i += 256) {
        int t = i / 51, c = i % 51;
        float4 v = reinterpret_cast<const float4*>(x_in + (size_t)sidx[t] * INF)[c];
        *reinterpret_cast<float4*>(&S[C_OFF + t * 212 + c * 4]) = v;
    }
    for (int i = tid; i < TT * 32; i += 256) {
        int t = i >> 5, c = i & 31;
        float4 v = reinterpret_cast<const float4*>(hidden + (size_t)sidx[t] * HD)[c];
        *reinterpret_cast<float4*>(&S[HS_OFF + t * 132 + c * 4]) = v;
    }
    __syncthreads();

    // ---- fc1: XA = relu(X @ W1 + b1), K=204 (17 chunks of 12), N=128, micro 4x8 ----
    {
        const float* W = fc1w + m * INF * HD;
        const int t0 = (tid >> 4) * 4, c0 = (tid & 15) * 8;
        float acc[4][8];
        #pragma unroll
        for (int i = 0; i < 4; i++)
            #pragma unroll
            for (int j = 0; j < 8; j++) acc[i][j] = 0.f;

        for (int ch = 0; ch < 17; ch++) {
            const int k0 = ch * 12;
            for (int i = tid; i < 12 * 128; i += 256)
                S[E_OFF + i] = W[(k0 + (i >> 7)) * HD + (i & 127)];
            __syncthreads();
            #pragma unroll
            for (int kk = 0; kk < 12; kk++) {
                float a[4];
                #pragma unroll
                for (int i = 0; i < 4; i++) a[i] = S[C_OFF + (t0 + i) * 212 + k0 + kk];
                float4 b0 = *reinterpret_cast<const float4*>(&S[E_OFF + kk * 128 + c0]);
                float4 b1 = *reinterpret_cast<const float4*>(&S[E_OFF + kk * 128 + c0 + 4]);
                #pragma unroll
                for (int i = 0; i < 4; i++) {
                    acc[i][0] = fmaf(a[i], b0.x, acc[i][0]);
                    acc[i][1] = fmaf(a[i], b0.y, acc[i][1]);
                    acc[i][2] = fmaf(a[i], b0.z, acc[i][2]);
                    acc[i][3] = fmaf(a[i], b0.w, acc[i][3]);
                    acc[i][4] = fmaf(a[i], b1.x, acc[i][4]);
                    acc[i][5] = fmaf(a[i], b1.y, acc[i][5]);
                    acc[i][6] = fmaf(a[i], b1.z, acc[i][6]);
                    acc[i][7] = fmaf(a[i], b1.w, acc[i][7]);
                }
            }
            __syncthreads();
        }
        #pragma unroll
        for (int i = 0; i < 4; i++)
            #pragma unroll
            for (int j = 0; j < 8; j++)
                S[XA_OFF + (t0 + i) * 132 + c0 + j] =
                    fmaxf(acc[i][j] + fc1b[m * HD + c0 + j], 0.f);
    }
    __syncthreads();

    // ---- r/z gates: RZ = sigmoid(XA@wih[:,0:256] + H@whh[:,0:256] + bih+bhh), micro 4x16 ----
    {
        const int t0 = (tid >> 4) * 4, c0 = (tid & 15) * 16;
        float acc[4][16];
        #pragma unroll
        for (int i = 0; i < 4; i++)
            #pragma unroll
            for (int j = 0; j < 16; j++) acc[i][j] = 0.f;

        #pragma unroll 1
        for (int pass = 0; pass < 2; pass++) {
            const float* W = (pass ? whh : wih) + m * HD * 384;
            const int srcOff = pass ? HS_OFF : XA_OFF;
            for (int ch = 0; ch < 8; ch++) {
                const int k0 = ch * 16;
                for (int i = tid; i < 16 * 256; i += 256)
                    S[E_OFF + i] = W[(k0 + (i >> 8)) * 384 + (i & 255)];
                __syncthreads();
                #pragma unroll
                for (int kk = 0; kk < 16; kk++) {
                    float a[4];
                    #pragma unroll
                    for (int i = 0; i < 4; i++) a[i] = S[srcOff + (t0 + i) * 132 + k0 + kk];
                    #pragma unroll
                    for (int jv = 0; jv < 4; jv++) {
                        float4 b = *reinterpret_cast<const float4*>(&S[E_OFF + kk * 256 + c0 + jv * 4]);
                        #pragma unroll
                        for (int i = 0; i < 4; i++) {
                            acc[i][jv * 4 + 0] = fmaf(a[i], b.x, acc[i][jv * 4 + 0]);
                            acc[i][jv * 4 + 1] = fmaf(a[i], b.y, acc[i][jv * 4 + 1]);
                            acc[i][jv * 4 + 2] = fmaf(a[i], b.z, acc[i][jv * 4 + 2]);
                            acc[i][jv * 4 + 3] = fmaf(a[i], b.w, acc[i][jv * 4 + 3]);
                        }
                    }
                }
                __syncthreads();
            }
        }
        #pragma unroll
        for (int i = 0; i < 4; i++)
            #pragma unroll
            for (int j = 0; j < 16; j++) {
                int c = c0 + j;
                float v = acc[i][j] + bih[m * 384 + c] + bhh[m * 384 + c];
                S[RZ_OFF + (t0 + i) * 256 + c] = 1.f / (1.f + expf(-v));
            }
    }
    __syncthreads();

    // ---- inn = XA@wih[:,256:] + bih_n ; hn = H@whh[:,256:] + bhh_n, micro 4x8 ----
    #pragma unroll 1
    for (int pass = 0; pass < 2; pass++) {
        const float* W = (pass ? whh : wih) + m * HD * 384 + 256;
        const float* bb = (pass ? bhh : bih) + m * 384 + 256;
        const int srcOff = pass ? HS_OFF : XA_OFF;
        const int dstOff = pass ? HN_OFF : C_OFF;
        const int t0 = (tid >> 4) * 4, c0 = (tid & 15) * 8;
        float acc[4][8];
        #pragma unroll
        for (int i = 0; i < 4; i++)
            #pragma unroll
            for (int j = 0; j < 8; j++) acc[i][j] = 0.f;

        for (int ch = 0; ch < 8; ch++) {
            const int k0 = ch * 16;
            for (int i = tid; i < 16 * 128; i += 256)
                S[E_OFF + i] = W[(k0 + (i >> 7)) * 384 + (i & 127)];
            __syncthreads();
            #pragma unroll
            for (int kk = 0; kk < 16; kk++) {
                float a[4];
                #pragma unroll
                for (int i = 0; i < 4; i++) a[i] = S[srcOff + (t0 + i) * 132 + k0 + kk];
                float4 b0 = *reinterpret_cast<const float4*>(&S[E_OFF + kk * 128 + c0]);
                float4 b1 = *reinterpret_cast<const float4*>(&S[E_OFF + kk * 128 + c0 + 4]);
                #pragma unroll
                for (int i = 0; i < 4; i++) {
                    acc[i][0] = fmaf(a[i], b0.x, acc[i][0]);
                    acc[i][1] = fmaf(a[i], b0.y, acc[i][1]);
                    acc[i][2] = fmaf(a[i], b0.z, acc[i][2]);
                    acc[i][3] = fmaf(a[i], b0.w, acc[i][3]);
                    acc[i][4] = fmaf(a[i], b1.x, acc[i][4]);
                    acc[i][5] = fmaf(a[i], b1.y, acc[i][5]);
                    acc[i][6] = fmaf(a[i], b1.z, acc[i][6]);
                    acc[i][7] = fmaf(a[i], b1.w, acc[i][7]);
                }
            }
            __syncthreads();
        }
        #pragma unroll
        for (int i = 0; i < 4; i++)
            #pragma unroll
            for (int j = 0; j < 8; j++)
                S[dstOff + (t0 + i) * 132 + c0 + j] = acc[i][j] + bb[c0 + j];
        __syncthreads();
    }

    // ---- GRU elementwise; write hiddens output; h_new overwrites H in smem ----
    for (int e = tid; e < TT * HD; e += 256) {
        int t = e >> 7, hh = e & 127;
        float r    = S[RZ_OFF + t * 256 + hh];
        float z    = S[RZ_OFF + t * 256 + 128 + hh];
        float innv = S[C_OFF + t * 132 + hh];
        float hnv  = S[HN_OFF + t * 132 + hh];
        float hv   = S[HS_OFF + t * 132 + hh];
        float ng   = tanhf(fmaf(r, hnv, innv));
        float hnew = fmaf(z, hv - ng, ng);  // (1-z)*ng + z*h
        S[HS_OFF + t * 132 + hh] = hnew;
        if (t < nvalid) out_h[(size_t)sidx[t] * HD + hh] = hnew;
    }
    __syncthreads();

    // ---- fc2: q = h_new @ W2 + b2, write qs ----
    for (int i = tid; i < HD * AD; i += 256) S[E_OFF + i] = fc2w[m * HD * AD + i];
    __syncthreads();
    {
        const int t = tid >> 2, rep = tid & 3;
        float a0 = 0.f, a1 = 0.f, a2 = 0.f, a3 = 0.f;
        for (int k = 0; k < HD; k++) {
            float hv = S[HS_OFF + t * 132 + k];
            a0 = fmaf(hv, S[E_OFF + k * AD + rep], a0);
            a1 = fmaf(hv, S[E_OFF + k * AD + rep + 4], a1);
            a2 = fmaf(hv, S[E_OFF + k * AD + rep + 8], a2);
            if (rep < 2) a3 = fmaf(hv, S[E_OFF + k * AD + rep + 12], a3);
        }
        if (t < nvalid) {
            size_t o = (size_t)sidx[t] * AD;
            out_q[o + rep]     = a0 + fc2b[m * AD + rep];
            out_q[o + rep + 4] = a1 + fc2b[m * AD + rep + 4];
            out_q[o + rep + 8] = a2 + fc2b[m * AD + rep + 8];
            if (rep < 2) out_q[o + rep + 12] = a3 + fc2b[m * AD + rep + 12];
        }
    }
}

extern "C" void kernel_launch(void* const* d_in, const int* in_sizes, int n_in,
                              void* d_out, int out_size) {
    const float* x    = (const float*)d_in[0];
    const float* h    = (const float*)d_in[1];
    const float* fc1w = (const float*)d_in[2];
    const float* fc1b = (const float*)d_in[3];
    const float* wih  = (const float*)d_in[4];
    const float* whh  = (const float*)d_in[5];
    const float* bih  = (const float*)d_in[6];
    const float* bhh  = (const float*)d_in[7];
    const float* fc2w = (const float*)d_in[8];
    const float* fc2b = (const float*)d_in[9];
    const float* w1   = (const float*)d_in[10];
    const float* b1   = (const float*)d_in[11];
    const float* w2   = (const float*)d_in[12];
    const float* b2   = (const float*)d_in[13];
    const float* w3   = (const float*)d_in[14];
    const float* b3   = (const float*)d_in[15];
    const float* mk   = (const float*)d_in[16];
    const float* wq   = (const float*)d_in[17];
    const float* bq   = (const float*)d_in[18];
    const float* wk   = (const float*)d_in[19];
    const float* bk   = (const float*)d_in[20];
    const float* un   = (const float*)d_in[21];

    float* outq = (float*)d_out;
    float* outh = outq + (size_t)NTOK * AD;

    cudaFuncSetAttribute(main_kernel, cudaFuncAttributeMaxDynamicSharedMemorySize, SMEM_BYTES);

    reset_kernel<<<1, 32>>>();
    router_kernel<<<NTOK / 128, 128>>>(h, w1, b1, w2, b2, w3, b3, wq, bq, wk, bk, mk, un);
    main_kernel<<<dim3(512, NM), 256, SMEM_BYTES>>>(x, h, fc1w, fc1b, wih, whh, bih, bhh,
                                                    fc2w, fc2b, outq, outh);
}

// round 2
// speedup vs baseline: 1.9292x; 1.9292x over previous
#include <cuda_runtime.h>
#include <math.h>

#define NTOK 32768
#define INF  204
#define HD   128
#define NM   4
#define AD   14
#define KD   32
#define TT   64

// smem layout (float indices)
#define XAH_OFF 0            // [64][264]: XA cols 0:128, H cols 128:256
#define XAH_STR 264
#define X_OFF   16896        // [64][212]: gathered inputs (204 used)
#define X_STR   212
#define STG_OFF 30464        // staging: 2 x 12288 (gates) or 2 x 4352 (fc1)
#define GBUF    12288        // 32 rows x 384
#define FBUF    4352         // 34 rows x 128
#define SMEM_FLOATS (STG_OFF + 2*GBUF)
#define SMEM_BYTES  (SMEM_FLOATS*4)

__device__ int g_cnt[NM];
__device__ int g_list[NM * NTOK];
__device__ unsigned char g_sel[NTOK];

__device__ __forceinline__ unsigned smem_u32(const void* p) {
    return (unsigned)__cvta_generic_to_shared(p);
}
__device__ __forceinline__ void cpa16(unsigned d, const void* s) {
    asm volatile("cp.async.ca.shared.global [%0], [%1], 16;" :: "r"(d), "l"(s));
}
__device__ __forceinline__ void cpa_commit() { asm volatile("cp.async.commit_group;"); }
template<int N> __device__ __forceinline__ void cpa_wait() {
    asm volatile("cp.async.wait_group %0;" :: "n"(N));
}

// ---------------- router: per-token mechanism selection -> g_sel ----------------
__global__ void __launch_bounds__(256) router_kernel(
    const float* __restrict__ hidden,
    const float* __restrict__ w1, const float* __restrict__ b1,
    const float* __restrict__ w2, const float* __restrict__ b2,
    const float* __restrict__ w3, const float* __restrict__ b3,
    const float* __restrict__ wq, const float* __restrict__ bq,
    const float* __restrict__ wk, const float* __restrict__ bk,
    const float* __restrict__ mkeys,
    const float* __restrict__ unif)
{
    __shared__ float w1s[HD * KD];
    __shared__ float w2s[KD * KD];
    __shared__ float w3s[KD * KD];
    __shared__ float wqs[KD * KD];
    __shared__ float kps[NM * KD];
    const int tid = threadIdx.x;

    for (int i = tid; i < HD * KD; i += 256) w1s[i] = w1[i];
    for (int i = tid; i < KD * KD; i += 256) {
        w2s[i] = w2[i]; w3s[i] = w3[i]; wqs[i] = wq[i];
    }
    if (tid < NM * KD) {
        int m = tid / KD, j = tid % KD;
        float acc = bk[j];
        #pragma unroll
        for (int k = 0; k < KD; k++) acc = fmaf(mkeys[m * KD + k], wk[k * KD + j], acc);
        kps[tid] = acc;
    }
    __syncthreads();

    const int t = blockIdx.x * 256 + tid;
    const float* h = hidden + (size_t)t * HD;

    float q1[KD];
    #pragma unroll
    for (int j = 0; j < KD; j++) q1[j] = b1[j];
    for (int k = 0; k < HD; k++) {
        float hk = __ldg(h + k);
        #pragma unroll
        for (int j = 0; j < KD; j++) q1[j] = fmaf(hk, w1s[k * KD + j], q1[j]);
    }
    #pragma unroll
    for (int j = 0; j < KD; j++) q1[j] = fmaxf(q1[j], 0.f);

    float q2[KD];
    #pragma unroll
    for (int j = 0; j < KD; j++) {
        float acc = b2[j];
        #pragma unroll
        for (int k = 0; k < KD; k++) acc = fmaf(q1[k], w2s[k * KD + j], acc);
        q2[j] = fmaxf(acc, 0.f);
    }
    float q3[KD];
    #pragma unroll
    for (int j = 0; j < KD; j++) {
        float acc = b3[j];
        #pragma unroll
        for (int k = 0; k < KD; k++) acc = fmaf(q2[k], w3s[k * KD + j], acc);
        q3[j] = acc;
    }
    float qpv[KD];
    #pragma unroll
    for (int j = 0; j < KD; j++) {
        float acc = bq[j];
        #pragma unroll
        for (int k = 0; k < KD; k++) acc = fmaf(q3[k], wqs[k * KD + j], acc);
        qpv[j] = acc;
    }

    float l[NM];
    #pragma unroll
    for (int mm = 0; mm < NM; mm++) {
        float acc = 0.f;
        #pragma unroll
        for (int j = 0; j < KD; j++) acc = fmaf(qpv[j], kps[mm * KD + j], acc);
        l[mm] = acc * 0.17677669529663687f;  // 1/sqrt(32)
    }
    float mx = fmaxf(fmaxf(l[0], l[1]), fmaxf(l[2], l[3]));
    float s = 0.f;
    #pragma unroll
    for (int mm = 0; mm < NM; mm++) { l[mm] = expf(l[mm] - mx); s += l[mm]; }
    float inv = 1.f / s;

    float best = -1e30f; int sel = 0;
    #pragma unroll
    for (int mm = 0; mm < NM; mm++) {
        float u = unif[(size_t)t * NM + mm];
        float g = -logf(-logf(u + 1e-10f) + 1e-10f);
        float y = fmaf(l[mm], inv, g);
        if (y > best) { best = y; sel = mm; }   // first-max on ties, like jnp.argmax
    }
    g_sel[t] = (unsigned char)sel;
}

// ---------------- compact: deterministic bucket build (1 block) ----------------
__global__ void __launch_bounds__(1024) compact_kernel() {
    __shared__ int scnt[NM * 1024];
    const int tid = threadIdx.x;
    const int t0 = tid * 32;

    unsigned char sel[32];
    int c0 = 0, c1 = 0, c2 = 0, c3 = 0;
    #pragma unroll
    for (int i = 0; i < 32; i++) {
        unsigned char s = g_sel[t0 + i];
        sel[i] = s;
        if (s == 0) c0++; else if (s == 1) c1++; else if (s == 2) c2++; else c3++;
    }
    scnt[0 * 1024 + tid] = c0;
    scnt[1 * 1024 + tid] = c1;
    scnt[2 * 1024 + tid] = c2;
    scnt[3 * 1024 + tid] = c3;
    __syncthreads();

    if (tid < NM * 32) {
        int m = tid >> 5, lane = tid & 31;
        int* a = &scnt[m * 1024 + lane * 32];
        int s = 0;
        #pragma unroll
        for (int k = 0; k < 32; k++) s += a[k];
        int incl = s;
        #pragma unroll
        for (int d = 1; d < 32; d <<= 1) {
            int v = __shfl_up_sync(0xffffffffu, incl, d);
            if (lane >= d) incl += v;
        }
        int run = incl - s;   // exclusive base for this lane's chunk
        #pragma unroll
        for (int k = 0; k < 32; k++) { int v = a[k]; a[k] = run; run += v; }
        if (lane == 31) g_cnt[m] = incl;
    }
    __syncthreads();

    int o0 = scnt[0 * 1024 + tid];
    int o1 = scnt[1 * 1024 + tid];
    int o2 = scnt[2 * 1024 + tid];
    int o3 = scnt[3 * 1024 + tid];
    #pragma unroll
    for (int i = 0; i < 32; i++) {
        int t = t0 + i;
        unsigned char s = sel[i];
        if (s == 0)      g_list[0 * NTOK + o0++] = t;
        else if (s == 1) g_list[1 * NTOK + o1++] = t;
        else if (s == 2) g_list[2 * NTOK + o2++] = t;
        else             g_list[3 * NTOK + o3++] = t;
    }
}

// ---------------- gates GEMM chunk: 32 K-rows, accumulate r/z + (n or hn) ----------------
__device__ __forceinline__ void gates_chunk(
    const float* __restrict__ B, const float* __restrict__ Sxah,
    int tw0, int c4, int kbase,
    float (&aR)[8][4], float (&aZ)[8][4], float (&aN)[8][4])
{
    #pragma unroll 4
    for (int kk = 0; kk < 32; kk++) {
        const float* brow = B + kk * 384;
        float4 br = *reinterpret_cast<const float4*>(brow + c4);
        float4 bz = *reinterpret_cast<const float4*>(brow + 128 + c4);
        float4 bn = *reinterpret_cast<const float4*>(brow + 256 + c4);
        const int k = kbase + kk;
        #pragma unroll
        for (int i = 0; i < 8; i++) {
            float a = Sxah[(tw0 + i) * XAH_STR + k];
            aR[i][0] = fmaf(a, br.x, aR[i][0]); aR[i][1] = fmaf(a, br.y, aR[i][1]);
            aR[i][2] = fmaf(a, br.z, aR[i][2]); aR[i][3] = fmaf(a, br.w, aR[i][3]);
            aZ[i][0] = fmaf(a, bz.x, aZ[i][0]); aZ[i][1] = fmaf(a, bz.y, aZ[i][1]);
            aZ[i][2] = fmaf(a, bz.z, aZ[i][2]); aZ[i][3] = fmaf(a, bz.w, aZ[i][3]);
            aN[i][0] = fmaf(a, bn.x, aN[i][0]); aN[i][1] = fmaf(a, bn.y, aN[i][1]);
            aN[i][2] = fmaf(a, bn.z, aN[i][2]); aN[i][3] = fmaf(a, bn.w, aN[i][3]);
        }
    }
}

// ---------------- main: fused fc1 -> GRU gates -> GRU -> fc2, per 64-token tile ----------------
__global__ void __launch_bounds__(256, 1) main_kernel(
    const float* __restrict__ x_in, const float* __restrict__ hidden,
    const float* __restrict__ fc1w, const float* __restrict__ fc1b,
    const float* __restrict__ wih,  const float* __restrict__ whh,
    const float* __restrict__ bih,  const float* __restrict__ bhh,
    const float* __restrict__ fc2w, const float* __restrict__ fc2b,
    float* __restrict__ out_q, float* __restrict__ out_h)
{
    extern __shared__ float S[];
    __shared__ int sidx[TT];
    const int m = blockIdx.y;
    const int cnt = g_cnt[m];
    const int base = blockIdx.x * TT;
    if (base >= cnt) return;
    const int nvalid = min(TT, cnt - base);
    const int tid = threadIdx.x;

    if (tid < TT) {
        int p = min(base + tid, cnt - 1);
        sidx[tid] = g_list[m * NTOK + p];
    }
    __syncthreads();

    const unsigned sb = smem_u32(S);
    const int tw0 = (tid >> 5) * 8;      // this warp's token base
    const int c4  = (tid & 31) * 4;      // this lane's column base

    // --- group0: gather X rows (51 vec4) and H rows (32 vec4, into XAH cols 128:256)
    for (int i = tid; i < TT * 51; i += 256) {
        int t = i / 51, c = i - t * 51;
        cpa16(sb + (unsigned)(X_OFF + t * X_STR + c * 4) * 4,
              x_in + (size_t)sidx[t] * INF + c * 4);
    }
    for (int i = tid; i < TT * 32; i += 256) {
        int t = i >> 5, c = i & 31;
        cpa16(sb + (unsigned)(XAH_OFF + t * XAH_STR + 128 + c * 4) * 4,
              hidden + (size_t)sidx[t] * HD + c * 4);
    }
    cpa_commit();

    // --- fc1: XA = relu(X @ W1 + b1), K=204 as 6 chunks of 34, double-buffered
    {
        const float* W = fc1w + (size_t)m * INF * HD;
        // issue chunk 0
        for (int i = tid; i < 1088; i += 256) {
            int row = i >> 5, c = i & 31;
            cpa16(sb + (unsigned)(STG_OFF + row * 128 + c * 4) * 4,
                  W + (size_t)row * HD + c * 4);
        }
        cpa_commit();

        float xacc[8][4];
        #pragma unroll
        for (int i = 0; i < 8; i++) { xacc[i][0]=0.f; xacc[i][1]=0.f; xacc[i][2]=0.f; xacc[i][3]=0.f; }

        for (int ch = 0; ch < 6; ch++) {
            if (ch + 1 < 6) {
                const float* Wn = W + (size_t)(ch + 1) * 34 * HD;
                const int boff = STG_OFF + ((ch + 1) & 1) * FBUF;
                for (int i = tid; i < 1088; i += 256) {
                    int row = i >> 5, c = i & 31;
                    cpa16(sb + (unsigned)(boff + row * 128 + c * 4) * 4,
                          Wn + (size_t)row * HD + c * 4);
                }
                cpa_commit();
                cpa_wait<1>();
            } else {
                cpa_wait<0>();
            }
            __syncthreads();
            const float* B = S + STG_OFF + (ch & 1) * FBUF;
            const float* Sx = S + X_OFF;
            const int kb = ch * 34;
            #pragma unroll 2
            for (int kk = 0; kk < 34; kk++) {
                float4 b = *reinterpret_cast<const float4*>(B + kk * 128 + c4);
                const int k = kb + kk;
                #pragma unroll
                for (int i = 0; i < 8; i++) {
                    float a = Sx[(tw0 + i) * X_STR + k];
                    xacc[i][0] = fmaf(a, b.x, xacc[i][0]);
                    xacc[i][1] = fmaf(a, b.y, xacc[i][1]);
                    xacc[i][2] = fmaf(a, b.z, xacc[i][2]);
                    xacc[i][3] = fmaf(a, b.w, xacc[i][3]);
                }
            }
            __syncthreads();
        }
        // epilogue: bias + relu -> XA region of XAH
        const float* fb = fc1b + (size_t)m * HD;
        float b0 = __ldg(fb + c4), b1 = __ldg(fb + c4 + 1), b2 = __ldg(fb + c4 + 2), b3 = __ldg(fb + c4 + 3);
        #pragma unroll
        for (int i = 0; i < 8; i++) {
            float4 v;
            v.x = fmaxf(xacc[i][0] + b0, 0.f);
            v.y = fmaxf(xacc[i][1] + b1, 0.f);
            v.z = fmaxf(xacc[i][2] + b2, 0.f);
            v.w = fmaxf(xacc[i][3] + b3, 0.f);
            *reinterpret_cast<float4*>(&S[XAH_OFF + (tw0 + i) * XAH_STR + c4]) = v;
        }
    }

    // --- GRU gates: [XA|H](64x256) @ [wih;whh](256x384), K=256 as 8 chunks of 32
    float aR[8][4], aZ[8][4], aN[8][4], aH[8][4];
    #pragma unroll
    for (int i = 0; i < 8; i++)
        #pragma unroll
        for (int j = 0; j < 4; j++) { aR[i][j]=0.f; aZ[i][j]=0.f; aN[i][j]=0.f; aH[i][j]=0.f; }

    {
        const float* Wih = wih + (size_t)m * HD * 384;
        const float* Whh = whh + (size_t)m * HD * 384;
        // issue chunk 0 (rows 0..31 -> wih)
        for (int q = 0; q < 12; q++) {
            int idx = q * 256 + tid;
            int row = idx / 96, c = idx - row * 96;
            cpa16(sb + (unsigned)(STG_OFF + row * 384 + c * 4) * 4,
                  Wih + (size_t)row * 384 + c * 4);
        }
        cpa_commit();

        for (int ch = 0; ch < 8; ch++) {
            if (ch + 1 < 8) {
                const int r0 = (ch + 1) * 32;
                const int boff = STG_OFF + ((ch + 1) & 1) * GBUF;
                for (int q = 0; q < 12; q++) {
                    int idx = q * 256 + tid;
                    int row = idx / 96, c = idx - row * 96;
                    int rg = r0 + row;
                    const float* src = (rg < 128) ? (Wih + (size_t)rg * 384)
                                                  : (Whh + (size_t)(rg - 128) * 384);
                    cpa16(sb + (unsigned)(boff + row * 384 + c * 4) * 4, src + c * 4);
                }
                cpa_commit();
                cpa_wait<1>();
            } else {
                cpa_wait<0>();
            }
            __syncthreads();
            const float* B = S + STG_OFF + (ch & 1) * GBUF;
            if (ch < 4) gates_chunk(B, S + XAH_OFF, tw0, c4, ch * 32, aR, aZ, aN);
            else        gates_chunk(B, S + XAH_OFF, tw0, c4, ch * 32, aR, aZ, aH);
            __syncthreads();
        }
    }

    // --- GRU elementwise in registers; write h_new to smem + gmem
    {
        const float* bi = bih + (size_t)m * 384;
        const float* bh = bhh + (size_t)m * 384;
        float brz[4], bzz[4], bin[4], bhn[4];
        #pragma unroll
        for (int j = 0; j < 4; j++) {
            int c = c4 + j;
            brz[j] = __ldg(bi + c)       + __ldg(bh + c);
            bzz[j] = __ldg(bi + 128 + c) + __ldg(bh + 128 + c);
            bin[j] = __ldg(bi + 256 + c);
            bhn[j] = __ldg(bh + 256 + c);
        }
        #pragma unroll
        for (int i = 0; i < 8; i++) {
            const int t = tw0 + i;
            float* hrow = &S[XAH_OFF + t * XAH_STR + 128];
            float4 hv4;
            #pragma unroll
            for (int j = 0; j < 4; j++) {
                float r  = 1.f / (1.f + expf(-(aR[i][j] + brz[j])));
                float z  = 1.f / (1.f + expf(-(aZ[i][j] + bzz[j])));
                float hn = aH[i][j] + bhn[j];
                float ng = tanhf(fmaf(r, hn, aN[i][j] + bin[j]));
                float h0 = hrow[c4 + j];
                float v  = fmaf(z, h0 - ng, ng);     // (1-z)*ng + z*h
                hrow[c4 + j] = v;
                (&hv4.x)[j] = v;
            }
            if (t < nvalid)
                *reinterpret_cast<float4*>(&out_h[(size_t)sidx[t] * HD + c4]) = hv4;
        }
    }
    __syncthreads();

    // --- fc2: q = h_new @ W2 + b2
    for (int i = tid; i < HD * AD; i += 256) S[STG_OFF + i] = fc2w[(size_t)m * HD * AD + i];
    __syncthreads();
    {
        const int t = tid >> 2, rep = tid & 3;
        const float* hrow = &S[XAH_OFF + t * XAH_STR + 128];
        float a0 = 0.f, a1 = 0.f, a2 = 0.f, a3 = 0.f;
        for (int k = 0; k < HD; k++) {
            float hv = hrow[k];
            a0 = fmaf(hv, S[STG_OFF + k * AD + rep], a0);
            a1 = fmaf(hv, S[STG_OFF + k * AD + rep + 4], a1);
            a2 = fmaf(hv, S[STG_OFF + k * AD + rep + 8], a2);
            if (rep < 2) a3 = fmaf(hv, S[STG_OFF + k * AD + rep + 12], a3);
        }
        if (t < nvalid) {
            const float* b2p = fc2b + (size_t)m * AD;
            size_t o = (size_t)sidx[t] * AD;
            out_q[o + rep]     = a0 + __ldg(b2p + rep);
            out_q[o + rep + 4] = a1 + __ldg(b2p + rep + 4);
            out_q[o + rep + 8] = a2 + __ldg(b2p + rep + 8);
            if (rep < 2) out_q[o + rep + 12] = a3 + __ldg(b2p + rep + 12);
        }
    }
}

extern "C" void kernel_launch(void* const* d_in, const int* in_sizes, int n_in,
                              void* d_out, int out_size) {
    const float* x    = (const float*)d_in[0];
    const float* h    = (const float*)d_in[1];
    const float* fc1w = (const float*)d_in[2];
    const float* fc1b = (const float*)d_in[3];
    const float* wih  = (const float*)d_in[4];
    const float* whh  = (const float*)d_in[5];
    const float* bih  = (const float*)d_in[6];
    const float* bhh  = (const float*)d_in[7];
    const float* fc2w = (const float*)d_in[8];
    const float* fc2b = (const float*)d_in[9];
    const float* w1   = (const float*)d_in[10];
    const float* b1   = (const float*)d_in[11];
    const float* w2   = (const float*)d_in[12];
    const float* b2   = (const float*)d_in[13];
    const float* w3   = (const float*)d_in[14];
    const float* b3   = (const float*)d_in[15];
    const float* mk   = (const float*)d_in[16];
    const float* wq   = (const float*)d_in[17];
    const float* bq   = (const float*)d_in[18];
    const float* wk   = (const float*)d_in[19];
    const float* bk   = (const float*)d_in[20];
    const float* un   = (const float*)d_in[21];

    float* outq = (float*)d_out;
    float* outh = outq + (size_t)NTOK * AD;

    cudaFuncSetAttribute(main_kernel, cudaFuncAttributeMaxDynamicSharedMemorySize, SMEM_BYTES);

    router_kernel<<<NTOK / 256, 256>>>(h, w1, b1, w2, b2, w3, b3, wq, bq, wk, bk, mk, un);
    compact_kernel<<<1, 1024>>>();
    main_kernel<<<dim3(512, NM), 256, SMEM_BYTES>>>(x, h, fc1w, fc1b, wih, whh, bih, bhh,
                                                    fc2w, fc2b, outq, outh);
}

// round 5
// speedup vs baseline: 3.4722x; 1.7998x over previous
#include <cuda_runtime.h>
#include <math.h>
#include <stdint.h>

#define NTOK 32768
#define INF  204
#define HD   128
#define NM   4
#define AD   14
#define KD   32
#define TT   64

// main kernel smem (float offsets)
#define SX 212
#define SH 132
#define OFF_X   0
#define OFF_H   (64*SX)               // 13568
#define OFF_STG (OFF_H + 64*SH)       // 22016
#define CHUNK_F 6144                  // 24KB max chunk
#define SMEM_MAIN_FLOATS (OFF_STG + 2*CHUNK_F + 64)
#define SMEM_MAIN_BYTES  (SMEM_MAIN_FLOATS*4)
#define SMEM_ROUTER (128*129*4)

#define STREAM_F 124928               // 13*2048 (fc1) + 16*6144 (gates)

__device__ __align__(16) float g_S[NM * STREAM_F];
__device__ int g_cnt[NM];
__device__ int g_list[NM * NTOK];
__device__ unsigned char g_sel[NTOK];

// ---------------- helpers ----------------
__device__ __forceinline__ uint32_t smem_u32(const void* p) {
    return (uint32_t)__cvta_generic_to_shared(p);
}
__device__ __forceinline__ void cpa16(uint32_t d, const void* s) {
    asm volatile("cp.async.ca.shared.global [%0], [%1], 16;" :: "r"(d), "l"(s));
}
__device__ __forceinline__ void cpa_commit() { asm volatile("cp.async.commit_group;"); }
template<int N> __device__ __forceinline__ void cpa_wait() {
    asm volatile("cp.async.wait_group %0;" :: "n"(N));
}
// m16n8k8 tf32 mma: D += A(16x8 row) * B(8x8 col)
__device__ __forceinline__ void mma8(float (&d)[4], const uint32_t (&a)[4],
                                     uint32_t b0, uint32_t b1) {
    asm volatile("mma.sync.aligned.m16n8k8.row.col.f32.tf32.tf32.f32 "
        "{%0,%1,%2,%3},{%4,%5,%6,%7},{%8,%9},{%0,%1,%2,%3};"
        : "+f"(d[0]), "+f"(d[1]), "+f"(d[2]), "+f"(d[3])
        : "r"(a[0]), "r"(a[1]), "r"(a[2]), "r"(a[3]), "r"(b0), "r"(b1));
}

// ---------------- prep: pack weights into per-lane fragment stream ----------------
// stream per mech: 13 fc1 chunks (2048 f) then 16 gates chunks (6144 f).
// chunk = 16 K-rows. layout [ntile][lane][4]: f = K sub-row 4f + lane%4, col 8*nt + lane/4
__global__ void __launch_bounds__(256) prep_kernel(
    const float* __restrict__ wih, const float* __restrict__ whh,
    const float* __restrict__ fc1w)
{
    const int bid = blockIdx.x;               // m*29 + i
    const int m = bid / 29, i = bid - m * 29;
    const int tid = threadIdx.x;
    float* dst = g_S + (size_t)m * STREAM_F + (i < 13 ? i * 2048 : 26624 + (i - 13) * 6144);
    const int total = (i < 13) ? 2048 : 6144;
    for (int o = tid; o < total; o += 256) {
        int nt = o >> 7, l = (o >> 2) & 31, f = o & 3;
        int kin = 4 * f + (l & 3);
        int n = 8 * nt + (l >> 2);
        float v;
        if (i < 13) {
            int k = 16 * i + kin;
            v = (k < INF) ? fc1w[(size_t)m * INF * HD + (size_t)k * HD + n] : 0.f;
        } else {
            int k = 16 * (i - 13) + kin;
            v = (k < 128) ? wih[(size_t)m * HD * 384 + (size_t)k * 384 + n]
                          : whh[(size_t)m * HD * 384 + (size_t)(k - 128) * 384 + n];
        }
        uint32_t t32;
        asm("cvt.rna.tf32.f32 %0, %1;" : "=r"(t32) : "f"(v));
        dst[o] = __uint_as_float(t32);
    }
}

// ---------------- router (fp32 exact, smem-staged H) ----------------
__global__ void __launch_bounds__(128) router_kernel(
    const float* __restrict__ hidden,
    const float* __restrict__ w1, const float* __restrict__ b1,
    const float* __restrict__ w2, const float* __restrict__ b2,
    const float* __restrict__ w3, const float* __restrict__ b3,
    const float* __restrict__ wq, const float* __restrict__ bq,
    const float* __restrict__ wk, const float* __restrict__ bk,
    const float* __restrict__ mkeys,
    const float* __restrict__ unif)
{
    extern __shared__ float HS[];      // [128][129]
    __shared__ float w1s[HD * KD], w2s[KD * KD], w3s[KD * KD], wqs[KD * KD], kps[NM * KD];
    const int tid = threadIdx.x;

    for (int i = tid; i < HD * KD; i += 128) w1s[i] = w1[i];
    for (int i = tid; i < KD * KD; i += 128) { w2s[i] = w2[i]; w3s[i] = w3[i]; wqs[i] = wq[i]; }
    if (tid < NM * KD) {
        int m = tid / KD, j = tid % KD;
        float acc = bk[j];
        #pragma unroll
        for (int k = 0; k < KD; k++) acc = fmaf(mkeys[m * KD + k], wk[k * KD + j], acc);
        kps[tid] = acc;
    }
    const size_t hb = (size_t)blockIdx.x * 128 * HD;
    for (int i = tid; i < 128 * HD; i += 128) {
        int t = i >> 7, c = i & 127;
        HS[t * 129 + c] = hidden[hb + (size_t)t * HD + c];
    }
    __syncthreads();

    const int t = blockIdx.x * 128 + tid;
    const float* h = &HS[tid * 129];
    float q1[KD];
    #pragma unroll
    for (int j = 0; j < KD; j++) q1[j] = b1[j];
    for (int k = 0; k < HD; k++) {
        float hk = h[k];
        #pragma unroll
        for (int j = 0; j < KD; j++) q1[j] = fmaf(hk, w1s[k * KD + j], q1[j]);
    }
    #pragma unroll
    for (int j = 0; j < KD; j++) q1[j] = fmaxf(q1[j], 0.f);
    float q2[KD];
    #pragma unroll
    for (int j = 0; j < KD; j++) {
        float a = b2[j];
        #pragma unroll
        for (int k = 0; k < KD; k++) a = fmaf(q1[k], w2s[k * KD + j], a);
        q2[j] = fmaxf(a, 0.f);
    }
    float q3[KD];
    #pragma unroll
    for (int j = 0; j < KD; j++) {
        float a = b3[j];
        #pragma unroll
        for (int k = 0; k < KD; k++) a = fmaf(q2[k], w3s[k * KD + j], a);
        q3[j] = a;
    }
    float qp[KD];
    #pragma unroll
    for (int j = 0; j < KD; j++) {
        float a = bq[j];
        #pragma unroll
        for (int k = 0; k < KD; k++) a = fmaf(q3[k], wqs[k * KD + j], a);
        qp[j] = a;
    }
    float lg[NM];
    #pragma unroll
    for (int mm = 0; mm < NM; mm++) {
        float a = 0.f;
        #pragma unroll
        for (int j = 0; j < KD; j++) a = fmaf(qp[j], kps[mm * KD + j], a);
        lg[mm] = a * 0.17677669529663687f;
    }
    float mx = fmaxf(fmaxf(lg[0], lg[1]), fmaxf(lg[2], lg[3]));
    float s = 0.f;
    #pragma unroll
    for (int mm = 0; mm < NM; mm++) { lg[mm] = expf(lg[mm] - mx); s += lg[mm]; }
    float inv = 1.f / s;
    float best = -1e30f; int sel = 0;
    #pragma unroll
    for (int mm = 0; mm < NM; mm++) {
        float u = unif[(size_t)t * NM + mm];
        float g = -logf(-logf(u + 1e-10f) + 1e-10f);
        float y = fmaf(lg[mm], inv, g);
        if (y > best) { best = y; sel = mm; }
    }
    g_sel[t] = (unsigned char)sel;
}

// ---------------- compact (deterministic, 1 block) ----------------
__global__ void __launch_bounds__(1024) compact_kernel() {
    __shared__ int scnt[NM * 1024];
    const int tid = threadIdx.x;
    const int t0 = tid * 32;
    unsigned char sel[32];
    int c0 = 0, c1 = 0, c2 = 0, c3 = 0;
    #pragma unroll
    for (int i = 0; i < 32; i++) {
        unsigned char s = g_sel[t0 + i]; sel[i] = s;
        if (s == 0) c0++; else if (s == 1) c1++; else if (s == 2) c2++; else c3++;
    }
    scnt[tid] = c0; scnt[1024 + tid] = c1; scnt[2048 + tid] = c2; scnt[3072 + tid] = c3;
    __syncthreads();
    if (tid < NM * 32) {
        int m = tid >> 5, lane = tid & 31;
        int* a = &scnt[m * 1024 + lane * 32];
        int s = 0;
        #pragma unroll
        for (int k = 0; k < 32; k++) s += a[k];
        int incl = s;
        #pragma unroll
        for (int d = 1; d < 32; d <<= 1) {
            int v = __shfl_up_sync(0xffffffffu, incl, d);
            if (lane >= d) incl += v;
        }
        int run = incl - s;
        #pragma unroll
        for (int k = 0; k < 32; k++) { int v = a[k]; a[k] = run; run += v; }
        if (lane == 31) g_cnt[m] = incl;
    }
    __syncthreads();
    int o0 = scnt[tid], o1 = scnt[1024 + tid], o2 = scnt[2048 + tid], o3 = scnt[3072 + tid];
    #pragma unroll
    for (int i = 0; i < 32; i++) {
        int t = t0 + i; unsigned char s = sel[i];
        if (s == 0) g_list[o0++] = t;
        else if (s == 1) g_list[NTOK + o1++] = t;
        else if (s == 2) g_list[2 * NTOK + o2++] = t;
        else g_list[3 * NTOK + o3++] = t;
    }
}

// gates double-kstep: accumulate r, z, and one of {inn, hn}
__device__ __forceinline__ void do_gates(
    const float* __restrict__ Ar, int stride, int col0,
    const float4 (&bg)[3][2], int ql, int qc,
    float (&gR)[2][4][4], float (&gZ)[2][4][4], float (&gNx)[2][4][4])
{
    #pragma unroll
    for (int ks = 0; ks < 2; ks++) {
        const int col = col0 + 8 * ks;
        uint32_t a[4][4];
        #pragma unroll
        for (int mt = 0; mt < 4; mt++) {
            const float* Ab = Ar + (16 * mt + ql) * stride + col + qc;
            a[mt][0] = __float_as_uint(Ab[0]);
            a[mt][1] = __float_as_uint(Ab[8 * stride]);
            a[mt][2] = __float_as_uint(Ab[4]);
            a[mt][3] = __float_as_uint(Ab[8 * stride + 4]);
        }
        #pragma unroll
        for (int j = 0; j < 2; j++) {
            uint32_t r0 = __float_as_uint(ks ? bg[0][j].z : bg[0][j].x);
            uint32_t r1 = __float_as_uint(ks ? bg[0][j].w : bg[0][j].y);
            uint32_t z0 = __float_as_uint(ks ? bg[1][j].z : bg[1][j].x);
            uint32_t z1 = __float_as_uint(ks ? bg[1][j].w : bg[1][j].y);
            uint32_t n0 = __float_as_uint(ks ? bg[2][j].z : bg[2][j].x);
            uint32_t n1 = __float_as_uint(ks ? bg[2][j].w : bg[2][j].y);
            #pragma unroll
            for (int mt = 0; mt < 4; mt++) {
                mma8(gR[j][mt], a[mt], r0, r1);
                mma8(gZ[j][mt], a[mt], z0, z1);
                mma8(gNx[j][mt], a[mt], n0, n1);
            }
        }
    }
}

// ---------------- main: mma.sync tf32 fused tile ----------------
__global__ void __launch_bounds__(256, 1) main_kernel(
    const float* __restrict__ x_in, const float* __restrict__ hidden,
    const float* __restrict__ fc1b,
    const float* __restrict__ bih, const float* __restrict__ bhh,
    const float* __restrict__ fc2w, const float* __restrict__ fc2b,
    float* __restrict__ out_q, float* __restrict__ out_h)
{
    extern __shared__ float S[];
    const int m = blockIdx.y;
    const int cnt = g_cnt[m];
    const int base = blockIdx.x * TT;
    if (base >= cnt) return;
    const int nvalid = min(TT, cnt - base);
    const int tid = threadIdx.x, w = tid >> 5, l = tid & 31;
    const int ql = l >> 2, qc = l & 3;

    int* sidx = (int*)(S + OFF_STG + 2 * CHUNK_F);
    if (tid < TT) sidx[tid] = g_list[m * NTOK + min(base + tid, cnt - 1)];
    // zero X pad cols 204..207 (NaN-poison guard: pad B is 0, NaN*0 = NaN)
    {
        int t = tid >> 2, c = 204 + (tid & 3);
        S[OFF_X + t * SX + c] = 0.f;
        S[OFF_X + (t + 64 > 63 ? t : t) * SX + c] = 0.f; // t in 0..63 ✓ (256 threads/4)
    }
    __syncthreads();

    const uint32_t sb = smem_u32(S);
    // group0: gather X (51 vec4/row) and H (32 vec4/row)
    for (int i = tid; i < TT * 51; i += 256) {
        int t = i / 51, c = i - t * 51;
        cpa16(sb + (uint32_t)(OFF_X + t * SX + c * 4) * 4,
              x_in + (size_t)sidx[t] * INF + c * 4);
    }
    for (int i = tid; i < TT * 32; i += 256) {
        int t = i >> 5, c = i & 31;
        cpa16(sb + (uint32_t)(OFF_H + t * SH + c * 4) * 4,
              hidden + (size_t)sidx[t] * HD + c * 4);
    }
    cpa_commit();
    // group1: chunk 0
    {
        const float* src = g_S + (size_t)m * STREAM_F;
        for (int q = tid; q < 512; q += 256)
            cpa16(sb + (uint32_t)(OFF_STG) * 4 + q * 16, src + q * 4);
        cpa_commit();
    }

    float fA[2][4][4];
    float gR[2][4][4], gZ[2][4][4], gN[2][4][4], gHn[2][4][4];
    #pragma unroll
    for (int j = 0; j < 2; j++)
        #pragma unroll
        for (int mt = 0; mt < 4; mt++)
            #pragma unroll
            for (int s = 0; s < 4; s++) {
                fA[j][mt][s] = 0.f; gR[j][mt][s] = 0.f; gZ[j][mt][s] = 0.f;
                gN[j][mt][s] = 0.f; gHn[j][mt][s] = 0.f;
            }

    for (int i = 0; i <= 28; i++) {
        const int buf = i & 1;
        if (i < 28) {
            const int ni = i + 1;
            const float* src = g_S + (size_t)m * STREAM_F +
                               (ni < 13 ? ni * 2048 : 26624 + (size_t)(ni - 13) * 6144);
            const int n4 = (ni < 13) ? 512 : 1536;
            const uint32_t dst = sb + (uint32_t)(OFF_STG + (buf ^ 1) * CHUNK_F) * 4;
            for (int q = tid; q < n4; q += 256) cpa16(dst + q * 16, src + q * 4);
            cpa_commit();
            cpa_wait<1>();
        } else {
            cpa_wait<0>();
        }
        __syncthreads();

        const float4* Bp = (const float4*)(S + OFF_STG + buf * CHUNK_F);
        if (i < 13) {
            // fc1: A = X (stride 212), warp cols 16w..16w+15 (ntiles 2w, 2w+1)
            float4 bf[2];
            bf[0] = Bp[(2 * w + 0) * 32 + l];
            bf[1] = Bp[(2 * w + 1) * 32 + l];
            #pragma unroll
            for (int ks = 0; ks < 2; ks++) {
                const int col = 16 * i + 8 * ks;
                uint32_t a[4][4];
                #pragma unroll
                for (int mt = 0; mt < 4; mt++) {
                    const float* Ab = S + OFF_X + (16 * mt + ql) * SX + col + qc;
                    a[mt][0] = __float_as_uint(Ab[0]);
                    a[mt][1] = __float_as_uint(Ab[8 * SX]);
                    a[mt][2] = __float_as_uint(Ab[4]);
                    a[mt][3] = __float_as_uint(Ab[8 * SX + 4]);
                }
                #pragma unroll
                for (int j = 0; j < 2; j++) {
                    uint32_t b0 = __float_as_uint(ks ? bf[j].z : bf[j].x);
                    uint32_t b1 = __float_as_uint(ks ? bf[j].w : bf[j].y);
                    #pragma unroll
                    for (int mt = 0; mt < 4; mt++) mma8(fA[j][mt], a[mt], b0, b1);
                }
            }
            if (i == 12) {
                // epilogue: relu+bias -> XA into X region cols 0..127
                // (safe: this chunk's A reads were cols 192..207)
                float bb[2][2];
                #pragma unroll
                for (int j = 0; j < 2; j++)
                    #pragma unroll
                    for (int p = 0; p < 2; p++)
                        bb[j][p] = __ldg(fc1b + m * HD + 16 * w + 8 * j + 2 * qc + p);
                #pragma unroll
                for (int j = 0; j < 2; j++)
                    #pragma unroll
                    for (int mt = 0; mt < 4; mt++)
                        #pragma unroll
                        for (int s = 0; s < 4; s++) {
                            int row = 16 * mt + ql + ((s >> 1) << 3);
                            int col = 16 * w + 8 * j + 2 * qc + (s & 1);
                            S[OFF_X + row * SX + col] =
                                fmaxf(fA[j][mt][s] + bb[j][s & 1], 0.f);
                        }
            }
        } else {
            const int c = i - 13;
            float4 bg[3][2];
            #pragma unroll
            for (int g = 0; g < 3; g++)
                #pragma unroll
                for (int j = 0; j < 2; j++)
                    bg[g][j] = Bp[(g * 16 + 2 * w + j) * 32 + l];
            if (c < 8) do_gates(S + OFF_X, SX, 16 * c, bg, ql, qc, gR, gZ, gN);
            else       do_gates(S + OFF_H, SH, 16 * c - 128, bg, ql, qc, gR, gZ, gHn);
        }
        __syncthreads();
    }

    // fc2 weights into (now free) staging
    float* Sw = S + OFF_STG;
    for (int i = tid; i < HD * AD; i += 256) Sw[i] = fc2w[(size_t)m * HD * AD + i];

    // GRU elementwise in registers; h_new -> H region
    {
        const float* bi = bih + (size_t)m * 384;
        const float* bh = bhh + (size_t)m * 384;
        float br[2][2], bz[2][2], bin[2][2], bhn[2][2];
        #pragma unroll
        for (int j = 0; j < 2; j++)
            #pragma unroll
            for (int p = 0; p < 2; p++) {
                int cb = 16 * w + 8 * j + 2 * qc + p;
                br[j][p]  = __ldg(bi + cb) + __ldg(bh + cb);
                bz[j][p]  = __ldg(bi + 128 + cb) + __ldg(bh + 128 + cb);
                bin[j][p] = __ldg(bi + 256 + cb);
                bhn[j][p] = __ldg(bh + 256 + cb);
            }
        #pragma unroll
        for (int j = 0; j < 2; j++)
            #pragma unroll
            for (int mt = 0; mt < 4; mt++)
                #pragma unroll
                for (int s = 0; s < 4; s++) {
                    int row = 16 * mt + ql + ((s >> 1) << 3);
                    int p = s & 1;
                    int col = 16 * w + 8 * j + 2 * qc + p;
                    float r  = 1.f / (1.f + expf(-(gR[j][mt][s] + br[j][p])));
                    float z  = 1.f / (1.f + expf(-(gZ[j][mt][s] + bz[j][p])));
                    float ng = tanhf(gN[j][mt][s] + bin[j][p] +
                                     r * (gHn[j][mt][s] + bhn[j][p]));
                    float h0 = S[OFF_H + row * SH + col];
                    S[OFF_H + row * SH + col] = fmaf(z, h0 - ng, ng);
                }
    }
    __syncthreads();

    // out_h (coalesced vec4)
    for (int i = tid; i < TT * 32; i += 256) {
        int t = i >> 5, g = i & 31;
        if (t < nvalid)
            *(float4*)(out_h + (size_t)sidx[t] * HD + g * 4) =
                *(float4*)(S + OFF_H + t * SH + g * 4);
    }

    // fc2: q = h_new @ W2 + b2 (fp32 scalar, 4 threads/token)
    {
        const int t = tid >> 2, rep = tid & 3;
        const float* hrow = S + OFF_H + t * SH;
        float a0 = 0.f, a1 = 0.f, a2 = 0.f, a3 = 0.f;
        for (int k = 0; k < HD; k++) {
            float hv = hrow[k];
            a0 = fmaf(hv, Sw[k * AD + rep], a0);
            a1 = fmaf(hv, Sw[k * AD + rep + 4], a1);
            a2 = fmaf(hv, Sw[k * AD + rep + 8], a2);
            if (rep < 2) a3 = fmaf(hv, Sw[k * AD + rep + 12], a3);
        }
        if (t < nvalid) {
            const float* b2p = fc2b + (size_t)m * AD;
            size_t o = (size_t)sidx[t] * AD;
            out_q[o + rep]     = a0 + __ldg(b2p + rep);
            out_q[o + rep + 4] = a1 + __ldg(b2p + rep + 4);
            out_q[o + rep + 8] = a2 + __ldg(b2p + rep + 8);
            if (rep < 2) out_q[o + rep + 12] = a3 + __ldg(b2p + rep + 12);
        }
    }
}

extern "C" void kernel_launch(void* const* d_in, const int* in_sizes, int n_in,
                              void* d_out, int out_size) {
    const float* x    = (const float*)d_in[0];
    const float* h    = (const float*)d_in[1];
    const float* fc1w = (const float*)d_in[2];
    const float* fc1b = (const float*)d_in[3];
    const float* wih  = (const float*)d_in[4];
    const float* whh  = (const float*)d_in[5];
    const float* bih  = (const float*)d_in[6];
    const float* bhh  = (const float*)d_in[7];
    const float* fc2w = (const float*)d_in[8];
    const float* fc2b = (const float*)d_in[9];
    const float* w1   = (const float*)d_in[10];
    const float* b1   = (const float*)d_in[11];
    const float* w2   = (const float*)d_in[12];
    const float* b2   = (const float*)d_in[13];
    const float* w3   = (const float*)d_in[14];
    const float* b3   = (const float*)d_in[15];
    const float* mk   = (const float*)d_in[16];
    const float* wq   = (const float*)d_in[17];
    const float* bq   = (const float*)d_in[18];
    const float* wk   = (const float*)d_in[19];
    const float* bk   = (const float*)d_in[20];
    const float* un   = (const float*)d_in[21];

    float* outq = (float*)d_out;
    float* outh = outq + (size_t)NTOK * AD;

    cudaFuncSetAttribute(main_kernel, cudaFuncAttributeMaxDynamicSharedMemorySize, SMEM_MAIN_BYTES);
    cudaFuncSetAttribute(router_kernel, cudaFuncAttributeMaxDynamicSharedMemorySize, SMEM_ROUTER);

    prep_kernel<<<NM * 29, 256>>>(wih, whh, fc1w);
    router_kernel<<<NTOK / 128, 128, SMEM_ROUTER>>>(h, w1, b1, w2, b2, w3, b3,
                                                    wq, bq, wk, bk, mk, un);
    compact_kernel<<<1, 1024>>>();
    main_kernel<<<dim3(NTOK / TT, NM), 256, SMEM_MAIN_BYTES>>>(x, h, fc1b, bih, bhh,
                                                               fc2w, fc2b, outq, outh);
}

// round 7
// speedup vs baseline: 3.4942x; 1.0063x over previous
#include <cuda_runtime.h>
#include <math.h>
#include <stdint.h>

#define NTOK 32768
#define INF  204
#define HD   128
#define NM   4
#define AD   14
#define KD   32
#define TT   64

// uniform weight chunks: 6144 floats (24KB). 5 fc1 chunks (48 K-rows x 128) + 16 gate chunks (16 K-rows x 384)
#define CH_F 6144
#define NCH  21
#define STREAM_F (NCH * CH_F)     // 129024 floats per mech

// main kernel smem (float offsets)
#define SX 212
#define SH 132
#define OFF_X   0                 // 64 x 212 = 13568
#define OFF_H   13568             // 64 x 132 = 8448
#define OFF_STG 22016             // 3 x 6144 staging
#define OFF_W2  (OFF_STG + 3*CH_F)   // 40448: fc2 weights 1792
#define OFF_AUX (OFF_W2 + 1792)      // 42240: sidx
#define SMEM_MAIN_FLOATS (OFF_AUX + 64)
#define SMEM_MAIN_BYTES  (SMEM_MAIN_FLOATS * 4)
#define SMEM_ROUTER (128 * 129 * 4)

__device__ __align__(16) float g_S[NM * STREAM_F];
__device__ int g_cnt[NM];
__device__ int g_list[NM * NTOK];
__device__ unsigned char g_sel[NTOK];

// ---------------- helpers ----------------
__device__ __forceinline__ uint32_t smem_u32(const void* p) {
    return (uint32_t)__cvta_generic_to_shared(p);
}
__device__ __forceinline__ void cpa16(uint32_t d, const void* s) {
    asm volatile("cp.async.ca.shared.global [%0], [%1], 16;" :: "r"(d), "l"(s));
}
__device__ __forceinline__ void cpa_commit() { asm volatile("cp.async.commit_group;"); }
template<int N> __device__ __forceinline__ void cpa_wait() {
    asm volatile("cp.async.wait_group %0;" :: "n"(N));
}
__device__ __forceinline__ void mma8(float (&d)[4], const uint32_t (&a)[4],
                                     uint32_t b0, uint32_t b1) {
    asm volatile("mma.sync.aligned.m16n8k8.row.col.f32.tf32.tf32.f32 "
        "{%0,%1,%2,%3},{%4,%5,%6,%7},{%8,%9},{%0,%1,%2,%3};"
        : "+f"(d[0]), "+f"(d[1]), "+f"(d[2]), "+f"(d[3])
        : "r"(a[0]), "r"(a[1]), "r"(a[2]), "r"(a[3]), "r"(b0), "r"(b1));
}
__device__ __forceinline__ float sigf(float x) {
    return 1.f / (1.f + __expf(-x));
}
__device__ __forceinline__ float tanhfast(float x) {
    return 1.f - 2.f / (__expf(2.f * x) + 1.f);   // saturates correctly at +/-1
}

// ---------------- merged router + prep ----------------
// blocks 0..255: router (128 tokens each). blocks 256..339: prep (NM*21 weight chunks).
__global__ void __launch_bounds__(128) router_prep_kernel(
    const float* __restrict__ hidden,
    const float* __restrict__ w1, const float* __restrict__ b1,
    const float* __restrict__ w2, const float* __restrict__ b2,
    const float* __restrict__ w3, const float* __restrict__ b3,
    const float* __restrict__ wq, const float* __restrict__ bq,
    const float* __restrict__ wk, const float* __restrict__ bk,
    const float* __restrict__ mkeys,
    const float* __restrict__ unif,
    const float* __restrict__ wih, const float* __restrict__ whh,
    const float* __restrict__ fc1w)
{
    const int tid = threadIdx.x;

    if (blockIdx.x >= 256) {
        // ---- prep: build per-lane tf32 fragment stream ----
        const int id = blockIdx.x - 256;         // m*21 + ch
        const int m = id / NCH, ch = id - m * NCH;
        float* dst = g_S + (size_t)m * STREAM_F + (size_t)ch * CH_F;
        for (int o = tid; o < CH_F; o += 128) {
            int f = o & 3, q = o >> 2;
            float v;
            if (ch < 5) {                        // fc1: 48 K-rows, [nt16][p3][lane][4]
                int nt = q / 96, r = q - nt * 96, p = r >> 5, l = r & 31;
                int k = 48 * ch + 16 * p + 4 * f + (l & 3);
                int n = 8 * nt + (l >> 2);
                v = (k < INF) ? fc1w[(size_t)m * INF * HD + (size_t)k * HD + n] : 0.f;
            } else {                             // gates: 16 K-rows, [nt48][lane][4]
                int j = ch - 5;
                int nt = q >> 5, l = q & 31;
                int k = 16 * j + 4 * f + (l & 3);
                int n = 8 * nt + (l >> 2);
                v = (k < 128) ? wih[(size_t)m * HD * 384 + (size_t)k * 384 + n]
                              : whh[(size_t)m * HD * 384 + (size_t)(k - 128) * 384 + n];
            }
            uint32_t t32;
            asm("cvt.rna.tf32.f32 %0, %1;" : "=r"(t32) : "f"(v));
            dst[o] = __uint_as_float(t32);
        }
        return;
    }

    // ---- router (fp32, bit-identical accumulation order to previous rounds) ----
    extern __shared__ float HS[];                // [128][129]
    __shared__ float w1s[HD * KD], w2s[KD * KD], w3s[KD * KD], wqs[KD * KD], kps[NM * KD];

    for (int i = tid; i < HD * KD; i += 128) w1s[i] = w1[i];
    for (int i = tid; i < KD * KD; i += 128) { w2s[i] = w2[i]; w3s[i] = w3[i]; wqs[i] = wq[i]; }
    if (tid < NM * KD) {
        int m = tid / KD, j = tid % KD;
        float acc = bk[j];
        #pragma unroll
        for (int k = 0; k < KD; k++) acc = fmaf(mkeys[m * KD + k], wk[k * KD + j], acc);
        kps[tid] = acc;
    }
    const size_t hb = (size_t)blockIdx.x * 128 * HD;
    for (int i = tid; i < 128 * HD; i += 128) {
        int t = i >> 7, c = i & 127;
        HS[t * 129 + c] = hidden[hb + (size_t)t * HD + c];
    }
    __syncthreads();

    const int t = blockIdx.x * 128 + tid;
    const float* h = &HS[tid * 129];
    float q1[KD];
    #pragma unroll
    for (int j = 0; j < KD; j++) q1[j] = b1[j];
    for (int k = 0; k < HD; k++) {
        float hk = h[k];
        const float4* wr = (const float4*)(w1s + k * KD);
        #pragma unroll
        for (int j4 = 0; j4 < 8; j4++) {
            float4 wv = wr[j4];
            q1[4*j4+0] = fmaf(hk, wv.x, q1[4*j4+0]);
            q1[4*j4+1] = fmaf(hk, wv.y, q1[4*j4+1]);
            q1[4*j4+2] = fmaf(hk, wv.z, q1[4*j4+2]);
            q1[4*j4+3] = fmaf(hk, wv.w, q1[4*j4+3]);
        }
    }
    #pragma unroll
    for (int j = 0; j < KD; j++) q1[j] = fmaxf(q1[j], 0.f);

    float q2[KD];
    #pragma unroll
    for (int j = 0; j < KD; j++) q2[j] = b2[j];
    #pragma unroll 4
    for (int k = 0; k < KD; k++) {
        float a = q1[k];
        const float4* wr = (const float4*)(w2s + k * KD);
        #pragma unroll
        for (int j4 = 0; j4 < 8; j4++) {
            float4 wv = wr[j4];
            q2[4*j4+0] = fmaf(a, wv.x, q2[4*j4+0]);
            q2[4*j4+1] = fmaf(a, wv.y, q2[4*j4+1]);
            q2[4*j4+2] = fmaf(a, wv.z, q2[4*j4+2]);
            q2[4*j4+3] = fmaf(a, wv.w, q2[4*j4+3]);
        }
    }
    #pragma unroll
    for (int j = 0; j < KD; j++) q2[j] = fmaxf(q2[j], 0.f);

    float q3[KD];
    #pragma unroll
    for (int j = 0; j < KD; j++) q3[j] = b3[j];
    #pragma unroll 4
    for (int k = 0; k < KD; k++) {
        float a = q2[k];
        const float4* wr = (const float4*)(w3s + k * KD);
        #pragma unroll
        for (int j4 = 0; j4 < 8; j4++) {
            float4 wv = wr[j4];
            q3[4*j4+0] = fmaf(a, wv.x, q3[4*j4+0]);
            q3[4*j4+1] = fmaf(a, wv.y, q3[4*j4+1]);
            q3[4*j4+2] = fmaf(a, wv.z, q3[4*j4+2]);
            q3[4*j4+3] = fmaf(a, wv.w, q3[4*j4+3]);
        }
    }

    float qp[KD];
    #pragma unroll
    for (int j = 0; j < KD; j++) qp[j] = bq[j];
    #pragma unroll 4
    for (int k = 0; k < KD; k++) {
        float a = q3[k];
        const float4* wr = (const float4*)(wqs + k * KD);
        #pragma unroll
        for (int j4 = 0; j4 < 8; j4++) {
            float4 wv = wr[j4];
            qp[4*j4+0] = fmaf(a, wv.x, qp[4*j4+0]);
            qp[4*j4+1] = fmaf(a, wv.y, qp[4*j4+1]);
            qp[4*j4+2] = fmaf(a, wv.z, qp[4*j4+2]);
            qp[4*j4+3] = fmaf(a, wv.w, qp[4*j4+3]);
        }
    }

    float lg[NM];
    #pragma unroll
    for (int mm = 0; mm < NM; mm++) {
        float a = 0.f;
        #pragma unroll
        for (int j = 0; j < KD; j++) a = fmaf(qp[j], kps[mm * KD + j], a);
        lg[mm] = a * 0.17677669529663687f;
    }
    float mx = fmaxf(fmaxf(lg[0], lg[1]), fmaxf(lg[2], lg[3]));
    float s = 0.f;
    #pragma unroll
    for (int mm = 0; mm < NM; mm++) { lg[mm] = expf(lg[mm] - mx); s += lg[mm]; }
    float inv = 1.f / s;
    float best = -1e30f; int sel = 0;
    #pragma unroll
    for (int mm = 0; mm < NM; mm++) {
        float u = unif[(size_t)t * NM + mm];
        float g = -logf(-logf(u + 1e-10f) + 1e-10f);
        float y = fmaf(lg[mm], inv, g);
        if (y > best) { best = y; sel = mm; }
    }
    g_sel[t] = (unsigned char)sel;
}

// ---------------- compact (deterministic, 1 block) ----------------
__global__ void __launch_bounds__(1024) compact_kernel() {
    __shared__ int scnt[NM * 1024];
    const int tid = threadIdx.x;
    const int t0 = tid * 32;
    unsigned char sel[32];
    int c0 = 0, c1 = 0, c2 = 0, c3 = 0;
    #pragma unroll
    for (int i = 0; i < 32; i++) {
        unsigned char s = g_sel[t0 + i]; sel[i] = s;
        if (s == 0) c0++; else if (s == 1) c1++; else if (s == 2) c2++; else c3++;
    }
    scnt[tid] = c0; scnt[1024 + tid] = c1; scnt[2048 + tid] = c2; scnt[3072 + tid] = c3;
    __syncthreads();
    if (tid < NM * 32) {
        int m = tid >> 5, lane = tid & 31;
        int* a = &scnt[m * 1024 + lane * 32];
        int s = 0;
        #pragma unroll
        for (int k = 0; k < 32; k++) s += a[k];
        int incl = s;
        #pragma unroll
        for (int d = 1; d < 32; d <<= 1) {
            int v = __shfl_up_sync(0xffffffffu, incl, d);
            if (lane >= d) incl += v;
        }
        int run = incl - s;
        #pragma unroll
        for (int k = 0; k < 32; k++) { int v = a[k]; a[k] = run; run += v; }
        if (lane == 31) g_cnt[m] = incl;
    }
    __syncthreads();
    int o0 = scnt[tid], o1 = scnt[1024 + tid], o2 = scnt[2048 + tid], o3 = scnt[3072 + tid];
    #pragma unroll
    for (int i = 0; i < 32; i++) {
        int t = t0 + i; unsigned char s = sel[i];
        if (s == 0) g_list[o0++] = t;
        else if (s == 1) g_list[NTOK + o1++] = t;
        else if (s == 2) g_list[2 * NTOK + o2++] = t;
        else g_list[3 * NTOK + o3++] = t;
    }
}

// gates chunk (16 K-rows): accumulate r, z, and one of {inn, hn}
__device__ __forceinline__ void do_gates(
    const float* __restrict__ Ar, int stride, int col0,
    const float4 (&bg)[3][2], int ql, int qc,
    float (&gR)[2][4][4], float (&gZ)[2][4][4], float (&gNx)[2][4][4])
{
    #pragma unroll
    for (int ks = 0; ks < 2; ks++) {
        const int col = col0 + 8 * ks;
        uint32_t a[4][4];
        #pragma unroll
        for (int mt = 0; mt < 4; mt++) {
            const float* Ab = Ar + (16 * mt + ql) * stride + col + qc;
            a[mt][0] = __float_as_uint(Ab[0]);
            a[mt][1] = __float_as_uint(Ab[8 * stride]);
            a[mt][2] = __float_as_uint(Ab[4]);
            a[mt][3] = __float_as_uint(Ab[8 * stride + 4]);
        }
        #pragma unroll
        for (int j = 0; j < 2; j++) {
            uint32_t r0 = __float_as_uint(ks ? bg[0][j].z : bg[0][j].x);
            uint32_t r1 = __float_as_uint(ks ? bg[0][j].w : bg[0][j].y);
            uint32_t z0 = __float_as_uint(ks ? bg[1][j].z : bg[1][j].x);
            uint32_t z1 = __float_as_uint(ks ? bg[1][j].w : bg[1][j].y);
            uint32_t n0 = __float_as_uint(ks ? bg[2][j].z : bg[2][j].x);
            uint32_t n1 = __float_as_uint(ks ? bg[2][j].w : bg[2][j].y);
            #pragma unroll
            for (int mt = 0; mt < 4; mt++) {
                mma8(gR[j][mt], a[mt], r0, r1);
                mma8(gZ[j][mt], a[mt], z0, z1);
                mma8(gNx[j][mt], a[mt], n0, n1);
            }
        }
    }
}

// ---------------- main: mma.sync tf32, 3-stage pipeline, 1 sync/iter ----------------
__global__ void __launch_bounds__(256, 1) main_kernel(
    const float* __restrict__ x_in, const float* __restrict__ hidden,
    const float* __restrict__ fc1b,
    const float* __restrict__ bih, const float* __restrict__ bhh,
    const float* __restrict__ fc2w, const float* __restrict__ fc2b,
    float* __restrict__ out_q, float* __restrict__ out_h)
{
    extern __shared__ float S[];
    const int m = blockIdx.y;
    const int cnt = g_cnt[m];
    const int base = blockIdx.x * TT;
    if (base >= cnt) return;
    const int nvalid = min(TT, cnt - base);
    const int tid = threadIdx.x, w = tid >> 5, l = tid & 31;
    const int ql = l >> 2, qc = l & 3;

    int* sidx = (int*)(S + OFF_AUX);
    if (tid < TT) sidx[tid] = g_list[m * NTOK + min(base + tid, cnt - 1)];
    // zero X pad cols 204..211 (beyond that, reads spill into neighbor rows: finite data x zero weights)
    {
        int t = tid >> 2, c = 204 + (tid & 3);
        S[OFF_X + t * SX + c] = 0.f;
        S[OFF_X + t * SX + c + 4] = 0.f;
    }
    __syncthreads();

    const uint32_t sb = smem_u32(S);
    // group0: X gather (51 vec4/row), H gather (32 vec4/row), fc2 weights (448 vec4)
    for (int i = tid; i < TT * 51; i += 256) {
        int t = i / 51, c = i - t * 51;
        cpa16(sb + (uint32_t)(OFF_X + t * SX + c * 4) * 4,
              x_in + (size_t)sidx[t] * INF + c * 4);
    }
    for (int i = tid; i < TT * 32; i += 256) {
        int t = i >> 5, c = i & 31;
        cpa16(sb + (uint32_t)(OFF_H + t * SH + c * 4) * 4,
              hidden + (size_t)sidx[t] * HD + c * 4);
    }
    for (int i = tid; i < 448; i += 256)
        cpa16(sb + (uint32_t)(OFF_W2) * 4 + i * 16,
              fc2w + (size_t)m * HD * AD + i * 4);
    cpa_commit();
    // stage chunks 0, 1
    const float* stream = g_S + (size_t)m * STREAM_F;
    for (int q = tid; q < 1536; q += 256)
        cpa16(sb + (uint32_t)(OFF_STG) * 4 + q * 16, stream + q * 4);
    cpa_commit();
    for (int q = tid; q < 1536; q += 256)
        cpa16(sb + (uint32_t)(OFF_STG + CH_F) * 4 + q * 16, stream + CH_F + q * 4);
    cpa_commit();

    float fA[2][4][4];
    float gR[2][4][4], gZ[2][4][4], gN[2][4][4], gHn[2][4][4];
    #pragma unroll
    for (int j = 0; j < 2; j++)
        #pragma unroll
        for (int mt = 0; mt < 4; mt++)
            #pragma unroll
            for (int s = 0; s < 4; s++) {
                fA[j][mt][s] = 0.f; gR[j][mt][s] = 0.f; gZ[j][mt][s] = 0.f;
                gN[j][mt][s] = 0.f; gHn[j][mt][s] = 0.f;
            }

    for (int i = 0; i < NCH; i++) {
        if (i == NCH - 1) cpa_wait<0>(); else cpa_wait<1>();
        __syncthreads();                          // single barrier per iteration
        if (i + 2 < NCH) {                        // issue stage i+2 (buffer last read at iter i-1)
            const float* src = stream + (size_t)(i + 2) * CH_F;
            const uint32_t dst = sb + (uint32_t)(OFF_STG + ((i + 2) % 3) * CH_F) * 4;
            for (int q = tid; q < 1536; q += 256) cpa16(dst + q * 16, src + q * 4);
            cpa_commit();
        }
        const float4* Bp = (const float4*)(S + OFF_STG + (i % 3) * CH_F);

        if (i < 5) {
            // fc1: 48 K-rows; warp owns ntiles 2w, 2w+1
            #pragma unroll
            for (int p = 0; p < 3; p++) {
                float4 b0 = Bp[((2 * w + 0) * 3 + p) * 32 + l];
                float4 b1 = Bp[((2 * w + 1) * 3 + p) * 32 + l];
                const int col0 = 48 * i + 16 * p;
                #pragma unroll
                for (int ks = 0; ks < 2; ks++) {
                    const int col = col0 + 8 * ks;
                    uint32_t a[4][4];
                    #pragma unroll
                    for (int mt = 0; mt < 4; mt++) {
                        const float* Ab = S + OFF_X + (16 * mt + ql) * SX + col + qc;
                        a[mt][0] = __float_as_uint(Ab[0]);
                        a[mt][1] = __float_as_uint(Ab[8 * SX]);
                        a[mt][2] = __float_as_uint(Ab[4]);
                        a[mt][3] = __float_as_uint(Ab[8 * SX + 4]);
                    }
                    uint32_t x0 = __float_as_uint(ks ? b0.z : b0.x);
                    uint32_t x1 = __float_as_uint(ks ? b0.w : b0.y);
                    uint32_t y0 = __float_as_uint(ks ? b1.z : b1.x);
                    uint32_t y1 = __float_as_uint(ks ? b1.w : b1.y);
                    #pragma unroll
                    for (int mt = 0; mt < 4; mt++) {
                        mma8(fA[0][mt], a[mt], x0, x1);
                        mma8(fA[1][mt], a[mt], y0, y1);
                    }
                }
            }
            if (i == 4) {
                // relu + bias -> XA into X region cols 0..127 (iter-5 sync orders readers)
                float bb[2][2];
                #pragma unroll
                for (int j = 0; j < 2; j++)
                    #pragma unroll
                    for (int p = 0; p < 2; p++)
                        bb[j][p] = __ldg(fc1b + m * HD + 16 * w + 8 * j + 2 * qc + p);
                #pragma unroll
                for (int j = 0; j < 2; j++)
                    #pragma unroll
                    for (int mt = 0; mt < 4; mt++)
                        #pragma unroll
                        for (int s = 0; s < 4; s++) {
                            int row = 16 * mt + ql + ((s >> 1) << 3);
                            int col = 16 * w + 8 * j + 2 * qc + (s & 1);
                            S[OFF_X + row * SX + col] =
                                fmaxf(fA[j][mt][s] + bb[j][s & 1], 0.f);
                        }
            }
        } else {
            const int c = i - 5;
            float4 bg[3][2];
            #pragma unroll
            for (int g = 0; g < 3; g++)
                #pragma unroll
                for (int j = 0; j < 2; j++)
                    bg[g][j] = Bp[(g * 16 + 2 * w + j) * 32 + l];
            if (c < 8) do_gates(S + OFF_X, SX, 16 * c, bg, ql, qc, gR, gZ, gN);
            else       do_gates(S + OFF_H, SH, 16 * c - 128, bg, ql, qc, gR, gZ, gHn);
        }
    }

    // GRU elementwise in registers; h_new -> H region (each thread owns its cells)
    {
        const float* bi = bih + (size_t)m * 384;
        const float* bh = bhh + (size_t)m * 384;
        float br[2][2], bz[2][2], bin[2][2], bhn[2][2];
        #pragma unroll
        for (int j = 0; j < 2; j++)
            #pragma unroll
            for (int p = 0; p < 2; p++) {
                int cb = 16 * w + 8 * j + 2 * qc + p;
                br[j][p]  = __ldg(bi + cb) + __ldg(bh + cb);
                bz[j][p]  = __ldg(bi + 128 + cb) + __ldg(bh + 128 + cb);
                bin[j][p] = __ldg(bi + 256 + cb);
                bhn[j][p] = __ldg(bh + 256 + cb);
            }
        #pragma unroll
        for (int j = 0; j < 2; j++)
            #pragma unroll
            for (int mt = 0; mt < 4; mt++)
                #pragma unroll
                for (int s = 0; s < 4; s++) {
                    int row = 16 * mt + ql + ((s >> 1) << 3);
                    int p = s & 1;
                    int col = 16 * w + 8 * j + 2 * qc + p;
                    float r  = sigf(gR[j][mt][s] + br[j][p]);
                    float z  = sigf(gZ[j][mt][s] + bz[j][p]);
                    float ng = tanhfast(gN[j][mt][s] + bin[j][p] +
                                        r * (gHn[j][mt][s] + bhn[j][p]));
                    float h0 = S[OFF_H + row * SH + col];
                    S[OFF_H + row * SH + col] = fmaf(z, h0 - ng, ng);
                }
    }
    __syncthreads();

    // out_h (coalesced vec4)
    for (int i = tid; i < TT * 32; i += 256) {
        int t = i >> 5, g = i & 31;
        if (t < nvalid)
            *(float4*)(out_h + (size_t)sidx[t] * HD + g * 4) =
                *(float4*)(S + OFF_H + t * SH + g * 4);
    }

    // fc2: q = h_new @ W2 + b2 (fp32 scalar, 4 threads/token; weights preloaded at OFF_W2)
    {
        const float* Sw = S + OFF_W2;
        const int t = tid >> 2, rep = tid & 3;
        const float* hrow = S + OFF_H + t * SH;
        float a0 = 0.f, a1 = 0.f, a2 = 0.f, a3 = 0.f;
        for (int k = 0; k < HD; k++) {
            float hv = hrow[k];
            a0 = fmaf(hv, Sw[k * AD + rep], a0);
            a1 = fmaf(hv, Sw[k * AD + rep + 4], a1);
            a2 = fmaf(hv, Sw[k * AD + rep + 8], a2);
            if (rep < 2) a3 = fmaf(hv, Sw[k * AD + rep + 12], a3);
        }
        if (t < nvalid) {
            const float* b2p = fc2b + (size_t)m * AD;
            size_t o = (size_t)sidx[t] * AD;
            out_q[o + rep]     = a0 + __ldg(b2p + rep);
            out_q[o + rep + 4] = a1 + __ldg(b2p + rep + 4);
            out_q[o + rep + 8] = a2 + __ldg(b2p + rep + 8);
            if (rep < 2) out_q[o + rep + 12] = a3 + __ldg(b2p + rep + 12);
        }
    }
}

extern "C" void kernel_launch(void* const* d_in, const int* in_sizes, int n_in,
                              void* d_out, int out_size) {
    const float* x    = (const float*)d_in[0];
    const float* h    = (const float*)d_in[1];
    const float* fc1w = (const float*)d_in[2];
    const float* fc1b = (const float*)d_in[3];
    const float* wih  = (const float*)d_in[4];
    const float* whh  = (const float*)d_in[5];
    const float* bih  = (const float*)d_in[6];
    const float* bhh  = (const float*)d_in[7];
    const float* fc2w = (const float*)d_in[8];
    const float* fc2b = (const float*)d_in[9];
    const float* w1   = (const float*)d_in[10];
    const float* b1   = (const float*)d_in[11];
    const float* w2   = (const float*)d_in[12];
    const float* b2   = (const float*)d_in[13];
    const float* w3   = (const float*)d_in[14];
    const float* b3   = (const float*)d_in[15];
    const float* mk   = (const float*)d_in[16];
    const float* wq   = (const float*)d_in[17];
    const float* bq   = (const float*)d_in[18];
    const float* wk   = (const float*)d_in[19];
    const float* bk   = (const float*)d_in[20];
    const float* un   = (const float*)d_in[21];

    float* outq = (float*)d_out;
    float* outh = outq + (size_t)NTOK * AD;

    cudaFuncSetAttribute(main_kernel, cudaFuncAttributeMaxDynamicSharedMemorySize, SMEM_MAIN_BYTES);
    cudaFuncSetAttribute(router_prep_kernel, cudaFuncAttributeMaxDynamicSharedMemorySize, SMEM_ROUTER);

    router_prep_kernel<<<256 + NM * NCH, 128, SMEM_ROUTER>>>(
        h, w1, b1, w2, b2, w3, b3, wq, bq, wk, bk, mk, un, wih, whh, fc1w);
    compact_kernel<<<1, 1024>>>();
    main_kernel<<<dim3(NTOK / TT, NM), 256, SMEM_MAIN_BYTES>>>(x, h, fc1b, bih, bhh,
                                                               fc2w, fc2b, outq, outh);
}